// round 7
// baseline (speedup 1.0000x reference)
#include <cuda_runtime.h>
#include <cuda_bf16.h>
#include <stdint.h>

#define CIN    16
#define COUT   32
#define KK     27
#define TPB    256
#define HBLK   256                        // h per block (2 per thread, o-split 2x16)
#define MAX_H  300064
#define MAX_B  2048

#define XPLANE 1032                       // words per quad-plane (256*4 + 8 pad)

__device__ float g_xt[(size_t)MAX_H * CIN];   // transposed x: [h][c]; row H = zeros
__device__ int   g_nk[(size_t)KK * MAX_H];    // clamped indices, [k][h] layout
__device__ float g_psum[MAX_B * COUT];
__device__ float g_psq [MAX_B * COUT];
__device__ float g_scale[COUT];
__device__ float g_shift[COUT];
__device__ int   g_is64;

typedef unsigned long long ull;

__device__ __forceinline__ void fma2(ull& d, ull a, ull b) {
    asm("fma.rn.f32x2 %0, %1, %2, %0;" : "+l"(d) : "l"(a), "l"(b));
}
__device__ __forceinline__ ull pack2(float v) {
    float2 t = make_float2(v, v);
    return *reinterpret_cast<ull*>(&t);
}
__device__ __forceinline__ void cp16(uint32_t dst_smem, const void* src) {
    asm volatile("cp.async.cg.shared.global [%0], [%1], 16;"
                 :: "r"(dst_smem), "l"(src));
}

// ---------------------------------------------------------------------------
__global__ void detect_kernel(const long long* __restrict__ neigh,
                              int H, long long n_elems) {
    __shared__ int bad;
    if (threadIdx.x == 0) bad = 0;
    __syncthreads();
    long long n64 = n_elems / 2;
    long long lim = n64 < 4096 ? n64 : 4096;
    for (long long i = threadIdx.x; i < lim; i += blockDim.x) {
        long long v = neigh[i];
        if (v < -1 || v >= (long long)H) bad = 1;
    }
    __syncthreads();
    if (threadIdx.x == 0) g_is64 = (bad == 0);
}

// ---------------------------------------------------------------------------
__global__ void prep_kernel(const void* __restrict__ neigh_raw, int H, int Hcover) {
    int h = blockIdx.x * blockDim.x + threadIdx.x;
    if (h >= Hcover) return;
    if (h >= H) {
#pragma unroll
        for (int k = 0; k < KK; k++) g_nk[(size_t)k * MAX_H + h] = H;
        return;
    }
    if (g_is64) {
        const long long* nrow = (const long long*)neigh_raw + (long long)h * KK;
#pragma unroll
        for (int k = 0; k < KK; k++) {
            long long v = nrow[k];
            g_nk[(size_t)k * MAX_H + h] = (v < 0 || v >= (long long)H) ? H : (int)v;
        }
    } else {
        const int* nrow = (const int*)neigh_raw + (long long)h * KK;
#pragma unroll
        for (int k = 0; k < KK; k++) {
            int v = nrow[k];
            g_nk[(size_t)k * MAX_H + h] = ((unsigned)v >= (unsigned)H) ? H : v;
        }
    }
}

// ---------------------------------------------------------------------------
__global__ void transpose_kernel(const float* __restrict__ x, int H) {
    int h = blockIdx.x * blockDim.x + threadIdx.x;
    float4* dst = reinterpret_cast<float4*>(&g_xt[(size_t)h * CIN]);
    if (h < H) {
        float v[CIN];
#pragma unroll
        for (int c = 0; c < CIN; c++) v[c] = x[(size_t)c * H + h];
#pragma unroll
        for (int j = 0; j < CIN / 4; j++)
            dst[j] = make_float4(v[4 * j], v[4 * j + 1], v[4 * j + 2], v[4 * j + 3]);
    } else if (h < H + 32 && h < MAX_H) {
        float4 z = make_float4(0.f, 0.f, 0.f, 0.f);
#pragma unroll
        for (int j = 0; j < CIN / 4; j++) dst[j] = z;
    }
}

// ---------------------------------------------------------------------------
// Gather-conv, block-shared x-tile + o-split:
//   per k: cp.async stages 256 gathered rows (64B each) into [quad][row]
//   planes; warps 0-3 compute o[0,16), warps 4-7 o[16,32); each thread 2 h.
// Weights [k][i][o] in smem; each broadcast LDS.128 feeds 4 fma2 (2 opairs x 2h).
// Accs: 16 u64 = 32 regs.
// ---------------------------------------------------------------------------
__global__ __launch_bounds__(TPB, 2)
void conv_kernel(const float* __restrict__ w,
                 float* __restrict__ out, int H) {
    extern __shared__ float smem[];
    float* ws = smem;                                 // 13824 floats
    float* xt = smem + KK * CIN * COUT;               // 4*XPLANE floats
    __shared__ float s_sum[TPB / 32][16];
    __shared__ float s_sq [TPB / 32][16];

    // ws[(k*CIN+i)*COUT + o] = w[(o*CIN+i)*KK + k]
    for (int idx = threadIdx.x; idx < KK * COUT * CIN; idx += TPB) {
        int k = idx / (CIN * COUT);
        int r = idx - k * (CIN * COUT);
        int i = r >> 5;
        int o = r & 31;
        ws[idx] = w[(o * CIN + i) * KK + k];
    }
    __syncthreads();

    int lane = threadIdx.x & 31;
    int warp = threadIdx.x >> 5;
    int ogrp  = warp >> 2;                  // 0 or 1
    int obase = ogrp * 16;
    int tloc  = (warp & 3) * 32 + lane;     // 0..127 within o-group
    int hbase = blockIdx.x * HBLK;
    int r0 = tloc, r1 = tloc + 128;
    int h0 = hbase + r0, h1 = hbase + r1;

    ull accA[8], accB[8];
#pragma unroll
    for (int m = 0; m < 8; m++) { accA[m] = 0ULL; accB[m] = 0ULL; }

    const int* nkbase = g_nk + hbase;

#pragma unroll 1
    for (int k = 0; k < KK; k++) {
        // ---- stage 256 rows via cp.async: 4 chunks of 16B per thread ----
        {
            const int* nk = nkbase + (size_t)k * MAX_H;
#pragma unroll
            for (int t = 0; t < 4; t++) {
                int c = t * TPB + threadIdx.x;        // 0..1023
                int row = c >> 2, q = c & 3;
                int n = nk[row];
                uint32_t dst = (uint32_t)__cvta_generic_to_shared(
                    &xt[q * XPLANE + row * 4]);
                cp16(dst, &g_xt[(size_t)n * CIN + q * 4]);
            }
            asm volatile("cp.async.commit_group;");
            asm volatile("cp.async.wait_group 0;" ::: "memory");
            __syncthreads();
        }

        // ---- compute ----
#pragma unroll
        for (int q = 0; q < 4; q++) {
            float4 va = *reinterpret_cast<const float4*>(&xt[q * XPLANE + r0 * 4]);
            float4 vb = *reinterpret_cast<const float4*>(&xt[q * XPLANE + r1 * 4]);
            float fa[4] = {va.x, va.y, va.z, va.w};
            float fb[4] = {vb.x, vb.y, vb.z, vb.w};
#pragma unroll
            for (int e = 0; e < 4; e++) {
                int i = q * 4 + e;
                ull xa = pack2(fa[e]);
                ull xb = pack2(fb[e]);
                const ulonglong2* wr = reinterpret_cast<const ulonglong2*>(
                    &ws[(k * CIN + i) * COUT + obase]);
#pragma unroll
                for (int m = 0; m < 4; m++) {
                    ulonglong2 wv = wr[m];            // broadcast LDS.128
                    fma2(accA[2 * m],     xa, wv.x);
                    fma2(accA[2 * m + 1], xa, wv.y);
                    fma2(accB[2 * m],     xb, wv.x);
                    fma2(accB[2 * m + 1], xb, wv.y);
                }
            }
        }
        __syncthreads();                              // tile reused next k
    }

    float ya[16], yb[16];
#pragma unroll
    for (int m = 0; m < 8; m++) {
        float2 pa = *reinterpret_cast<float2*>(&accA[m]);
        float2 pb = *reinterpret_cast<float2*>(&accB[m]);
        ya[2 * m] = pa.x; ya[2 * m + 1] = pa.y;
        yb[2 * m] = pb.x; yb[2 * m + 1] = pb.y;
    }

    if (h0 < H) {
#pragma unroll
        for (int o = 0; o < 16; o++) out[(size_t)(obase + o) * H + h0] = ya[o];
    }
    if (h1 < H) {
#pragma unroll
        for (int o = 0; o < 16; o++) out[(size_t)(obase + o) * H + h1] = yb[o];
    }

    // --- deterministic block reduction (h>=H rows are exact 0) ---
#pragma unroll
    for (int o = 0; o < 16; o++) {
        float v  = ya[o] + yb[o];
        float v2 = ya[o] * ya[o] + yb[o] * yb[o];
#pragma unroll
        for (int off = 16; off > 0; off >>= 1) {
            v  += __shfl_xor_sync(0xFFFFFFFFu, v,  off);
            v2 += __shfl_xor_sync(0xFFFFFFFFu, v2, off);
        }
        if (lane == 0) { s_sum[warp][o] = v; s_sq[warp][o] = v2; }
    }
    __syncthreads();
    if (threadIdx.x < COUT) {
        int o = threadIdx.x;
        int wbase = (o < 16) ? 0 : 4;
        int oc = o & 15;
        float S = 0.0f, Q = 0.0f;
#pragma unroll
        for (int wdx = 0; wdx < 4; wdx++) {
            S += s_sum[wbase + wdx][oc];
            Q += s_sq [wbase + wdx][oc];
        }
        g_psum[(size_t)blockIdx.x * COUT + o] = S;
        g_psq [(size_t)blockIdx.x * COUT + o] = Q;
    }
}

// ---------------------------------------------------------------------------
__global__ void stats_kernel(const float* __restrict__ gamma,
                             const float* __restrict__ beta,
                             int H, int NB) {
    int o = blockIdx.x;
    float S = 0.0f, Q = 0.0f;
    for (int b = threadIdx.x; b < NB; b += blockDim.x) {
        S += g_psum[(size_t)b * COUT + o];
        Q += g_psq [(size_t)b * COUT + o];
    }
    __shared__ float ss[256], sq[256];
    ss[threadIdx.x] = S;
    sq[threadIdx.x] = Q;
    __syncthreads();
    for (int off = 128; off > 0; off >>= 1) {
        if (threadIdx.x < off) {
            ss[threadIdx.x] += ss[threadIdx.x + off];
            sq[threadIdx.x] += sq[threadIdx.x + off];
        }
        __syncthreads();
    }
    if (threadIdx.x == 0) {
        float invH = 1.0f / (float)H;
        float mean = ss[0] * invH;
        float var  = sq[0] * invH - mean * mean;
        float sc   = gamma[o] * rsqrtf(var + 1e-5f);
        g_scale[o] = sc;
        g_shift[o] = beta[o] - mean * sc;
    }
}

// ---------------------------------------------------------------------------
__global__ void norm_kernel(float* __restrict__ out, int H) {
    int o = blockIdx.y;
    int i = blockIdx.x * blockDim.x + threadIdx.x;
    int H4 = H >> 2;
    float sc = g_scale[o], sh = g_shift[o];
    float4* p = reinterpret_cast<float4*>(out + (size_t)o * H);
    if (i < H4) {
        float4 v = p[i];
        v.x = v.x * sc + sh;
        v.y = v.y * sc + sh;
        v.z = v.z * sc + sh;
        v.w = v.w * sc + sh;
        p[i] = v;
    }
    if (blockIdx.x == 0 && threadIdx.x < (H & 3)) {
        int hh = H4 * 4 + threadIdx.x;
        out[(size_t)o * H + hh] = out[(size_t)o * H + hh] * sc + sh;
    }
}

// ---------------------------------------------------------------------------
extern "C" void kernel_launch(void* const* d_in, const int* in_sizes, int n_in,
                              void* d_out, int out_size) {
    const float* x     = (const float*)d_in[0];
    const float* w     = (const float*)d_in[1];
    const float* gamma = (const float*)d_in[2];
    const float* beta  = (const float*)d_in[3];
    const void*  neigh = d_in[4];

    int H  = in_sizes[0] / CIN;
    int NB = (H + HBLK - 1) / HBLK;
    int Hcover = NB * HBLK;
    long long n_neigh = (long long)in_sizes[4];

    static const int kSmemBytes =
        (KK * COUT * CIN + 4 * XPLANE) * (int)sizeof(float);   // 71808
    cudaFuncSetAttribute(conv_kernel,
                         cudaFuncAttributeMaxDynamicSharedMemorySize, kSmemBytes);

    detect_kernel<<<1, 256>>>((const long long*)neigh, H, n_neigh);
    prep_kernel<<<(Hcover + 255) / 256, 256>>>(neigh, H, Hcover);
    transpose_kernel<<<(H + 32 + 255) / 256, 256>>>(x, H);
    conv_kernel<<<NB, TPB, kSmemBytes>>>(w, (float*)d_out, H);
    stats_kernel<<<COUT, 256>>>(gamma, beta, H, NB);
    dim3 ngrid((H / 4 + 255) / 256, COUT);
    norm_kernel<<<ngrid, 256>>>((float*)d_out, H);
}